// round 14
// baseline (speedup 1.0000x reference)
#include <cuda_runtime.h>
#include <math.h>
#include <stdint.h>

#define BATCH 32
#define NV 1556
#define NI 256
#define NTOK 1812      // NV + NI
#define DM 512
#define IMGD 2048
#define NSLICE 8
#define SLROWS 227     // ceil(1812/8)
#define MB_PROJ 13     // ceil(NV/128) M-blocks per batch in proj GEMM

#define SOFTMAX_SCALE 0.088388347648318440550f  // (512/4)^-0.5

// ---------------------------------------------------------------------------
// Device-global scratch (no runtime allocation allowed).
// ---------------------------------------------------------------------------
__device__ float  g_Q[BATCH * NTOK * DM];      // raw q (pre-norm)
__device__ float  g_K[BATCH * NTOK * DM];      // raw k (pre-norm)
__device__ float  g_C[BATCH * NI * DM];        // compact img projection
__device__ float  g_P[BATCH * NV * DM];        // proj output (compact)
__device__ float  g_W[BATCH * DM * DM];        // Wg[b] = g_b (.) proj_w
__device__ float  g_G[BATCH * DM];             // global query g
__device__ float  g_L[BATCH * NTOK];           // logits -> a' weights
__device__ float  g_Gp[NSLICE * BATCH * DM];   // greduce partials
__device__ float2 g_PQ[BATCH * NTOK * 4];      // per-colblock (sumsq, dot wg)
__device__ float2 g_PK[BATCH * NTOK * 4];      // per-colblock (sumsq, 0)
__device__ float  g_IQ[BATCH * NTOK];          // 1/||q||
__device__ float  g_IK[BATCH * NTOK];          // 1/||k||

// ---------------------------------------------------------------------------
// PTX helpers — baseline sm_103 only (no 'a'-suffix features).
// ---------------------------------------------------------------------------
__device__ __forceinline__ uint32_t smem_u32(const void* p) {
    uint32_t a;
    asm("{ .reg .u64 t; cvta.to.shared.u64 t, %1; cvt.u32.u64 %0, t; }"
        : "=r"(a) : "l"(p));
    return a;
}

#define CP16(dst, src) \
    asm volatile("cp.async.cg.shared.global [%0], [%1], 16;" \
                 :: "r"(dst), "l"(src))
#define CP_COMMIT() asm volatile("cp.async.commit_group;" ::: "memory")
#define CP_WAIT1()  asm volatile("cp.async.wait_group 1;" ::: "memory")
#define CP_WAIT0()  asm volatile("cp.async.wait_group 0;" ::: "memory")

#define LDMATRIX_X4(r0, r1, r2, r3, addr) \
    asm volatile("ldmatrix.sync.aligned.m8n8.x4.shared.b16 {%0,%1,%2,%3}, [%4];" \
                 : "=r"(r0), "=r"(r1), "=r"(r2), "=r"(r3) : "r"(addr))

// raw fp32 bits as tf32 operands (round-toward-zero fast path).
#define MMA_TF32(c, a, b) \
    asm volatile("mma.sync.aligned.m16n8k8.row.col.f32.tf32.tf32.f32 " \
                 "{%0,%1,%2,%3}, {%4,%5,%6,%7}, {%8,%9}, {%0,%1,%2,%3};" \
                 : "+f"((c)[0]), "+f"((c)[1]), "+f"((c)[2]), "+f"((c)[3]) \
                 : "r"((a)[0]), "r"((a)[1]), "r"((a)[2]), "r"((a)[3]), \
                   "r"((b)[0]), "r"((b)[1]))

// ---------------------------------------------------------------------------
// cp.async 3-stage tf32 GEMM, block 128x128, BK=32, 8 warps (4M x 2N).
// B fragments register-double-buffered (LDSM for ks+1 overlaps MMA of ks);
// A fragments loaded per-ks (keeps regs ~124, 2 CTAs/SM).
//   MODE 0: plain linear A -> linear C             (img_f @ fc_w -> imgC)
//   MODE 1: A row-remap verts/imgC; C=raw Q; epilogue partial (sumsq, q.wg)
//   MODE 2: A row-remap verts/imgC; C=raw K; epilogue partial (sumsq, 0)
//   MODE 3: per-batch (grid.z=b): A=raw K rows (clamped), W=Wg[b];
//           epi: v = inv_k*acc + proj_b + inv_q*q_raw -> P compact
//   MODE 4: linear; epi += verts residual -> d_out
// ---------------------------------------------------------------------------
#define STG_BYTES 32768
#define SMEM_CA   (3 * STG_BYTES)    // 98304

template <int MODE>
__global__ void __launch_bounds__(256, 2) ca_gemm_k(
    const float* __restrict__ A, const float* __restrict__ A2,
    const float* __restrict__ W, const float* __restrict__ bias,
    float* __restrict__ C, int K,
    const float* __restrict__ E0, const float* __restrict__ E1,
    float2* __restrict__ PP)
{
    extern __shared__ uint32_t sm[];
    __shared__ float2 sred[128][2];
    const uint32_t sbase = smem_u32(sm);

    const int tid  = threadIdx.x;
    const int warp = tid >> 5;
    const int lane = tid & 31;
    const int row0 = blockIdx.y * 128;
    const int col0 = blockIdx.x * 128;
    const int bz   = (MODE == 3) ? blockIdx.z : 0;

    // ---- async-load addressing ----
    const int lrow   = tid >> 1;
    const int lchunk = (tid & 1) * 4;
    const int lxor   = lrow & 7;
    const int garow  = row0 + lrow;

    const float* Ag;
    if (MODE == 1 || MODE == 2) {
        const int b = garow / NTOK;
        const int n = garow - b * NTOK;
        Ag = (n < NV) ? A  + ((size_t)b * NV + n) * (size_t)K
                      : A2 + ((size_t)b * NI + (n - NV)) * (size_t)K;
    } else if (MODE == 3) {
        const int n = (garow < NV) ? garow : (NV - 1);
        Ag = A + ((size_t)bz * NTOK + n) * (size_t)K;
    } else {
        Ag = A + (size_t)garow * (size_t)K;
    }
    const float* Wg = ((MODE == 3) ? (W + (size_t)bz * DM * DM) : W)
                      + (size_t)(col0 + lrow) * (size_t)K;
    const uint32_t srowA = (uint32_t)(lrow << 3);

    // ---- warp tiling ----
    const int wm = warp >> 1;
    const int wn = warp & 1;
    const int arow_l = (lane & 7) + ((lane >> 3) & 1) * 8;
    const int brow_l = (lane & 7) + ((lane >> 4) & 1) * 8;
    const int acsel  = lane >> 4;
    const int bcsel  = (lane >> 3) & 1;
    const int fxor   = lane & 7;

    // fragment smem byte offsets (relative to stage base)
    uint32_t aoffs[2], boffs[4];
#pragma unroll
    for (int mt = 0; mt < 2; mt++) {
        const int row = wm * 32 + mt * 16 + arow_l;
        aoffs[mt] = (uint32_t)((row << 3) << 4);
    }
#pragma unroll
    for (int np = 0; np < 4; np++) {
        const int row = wn * 64 + np * 16 + brow_l;
        boffs[np] = (uint32_t)((row << 3) << 4);
    }

    float acc[2][8][4];
#pragma unroll
    for (int mt = 0; mt < 2; mt++)
#pragma unroll
        for (int nt = 0; nt < 8; nt++)
#pragma unroll
            for (int r = 0; r < 4; r++) acc[mt][nt][r] = 0.f;

    const int NT = K >> 5;

    auto stage_load = [&](int t, int slot) {
        const uint32_t sb = sbase + (uint32_t)slot * STG_BYTES;
        const int kof = t << 5;
#pragma unroll
        for (int i = 0; i < 4; i++) {
            const int c = lchunk + i;
            CP16(sb + ((srowA + (uint32_t)(c ^ lxor)) << 4), Ag + kof + c * 4);
        }
#pragma unroll
        for (int i = 0; i < 4; i++) {
            const int c = lchunk + i;
            CP16(sb + 16384u + ((srowA + (uint32_t)(c ^ lxor)) << 4),
                 Wg + kof + c * 4);
        }
        CP_COMMIT();
    };

    stage_load(0, 0);
    stage_load(1, 1);

    // B fragments double-buffered; A fragments per-ks
    uint32_t bf[2][8][2];
    uint32_t af[2][4];

    int slot = 0;
    for (int t = 0; t < NT; t++) {
        if (t < NT - 1) CP_WAIT1(); else CP_WAIT0();
        __syncthreads();

        const uint32_t abase = sbase + (uint32_t)slot * STG_BYTES;
        const uint32_t bbase = abase + 16384u;

        // preload B fragments for ks=0
#pragma unroll
        for (int np = 0; np < 4; np++) {
            uint32_t r0, r1, r2, r3;
            const uint32_t bd = bbase + boffs[np]
                + (uint32_t)(((0 + bcsel) ^ fxor) << 4);
            LDMATRIX_X4(r0, r1, r2, r3, bd);
            bf[0][np * 2 + 0][0] = r0; bf[0][np * 2 + 0][1] = r1;
            bf[0][np * 2 + 1][0] = r2; bf[0][np * 2 + 1][1] = r3;
        }

        // next-stage gmem prefetch (cp.async has 2 stages of slack)
        if (t + 2 < NT) {
            int ps = slot + 2; if (ps >= 3) ps -= 3;
            stage_load(t + 2, ps);
        }

#pragma unroll
        for (int ks = 0; ks < 4; ks++) {
            const int cb = ks & 1;
            // A fragments for current ks
#pragma unroll
            for (int mt = 0; mt < 2; mt++) {
                const uint32_t ad = abase + aoffs[mt]
                    + (uint32_t)(((ks * 2 + acsel) ^ fxor) << 4);
                LDMATRIX_X4(af[mt][0], af[mt][1], af[mt][2], af[mt][3], ad);
            }
            // prefetch B fragments for ks+1 (overlaps MMA below)
            if (ks < 3) {
                const int nb = cb ^ 1;
                const int kn = ks + 1;
#pragma unroll
                for (int np = 0; np < 4; np++) {
                    uint32_t r0, r1, r2, r3;
                    const uint32_t bd = bbase + boffs[np]
                        + (uint32_t)(((kn * 2 + bcsel) ^ fxor) << 4);
                    LDMATRIX_X4(r0, r1, r2, r3, bd);
                    bf[nb][np * 2 + 0][0] = r0; bf[nb][np * 2 + 0][1] = r1;
                    bf[nb][np * 2 + 1][0] = r2; bf[nb][np * 2 + 1][1] = r3;
                }
            }
#pragma unroll
            for (int mt = 0; mt < 2; mt++)
#pragma unroll
                for (int nt = 0; nt < 8; nt++)
                    MMA_TF32(acc[mt][nt], af[mt], bf[cb][nt]);
        }

        slot++; if (slot >= 3) slot -= 3;
    }

    // ---- epilogue ----
    const int orow  = lane >> 2;
    const int ocol2 = (lane & 3) * 2;

    float pss[2][2], pdot[2][2];
    if (MODE == 1 || MODE == 2) {
#pragma unroll
        for (int a = 0; a < 2; a++)
#pragma unroll
            for (int h = 0; h < 2; h++) { pss[a][h] = 0.f; pdot[a][h] = 0.f; }
    }

#pragma unroll
    for (int mt = 0; mt < 2; mt++) {
#pragma unroll
        for (int half = 0; half < 2; half++) {
            const int m = row0 + wm * 32 + mt * 16 + orow + half * 8;
            size_t crow = (size_t)m;
            size_t tok = 0;
            bool live = true;
            if (MODE == 3) {
                if (m >= NV) live = false;
                tok  = (size_t)bz * NTOK + m;
                crow = (size_t)bz * NV + m;
            }
            float ik = 1.f, iq = 0.f;
            if (MODE == 3 && live) { ik = E0[tok]; iq = E1[tok]; }
#pragma unroll
            for (int nt = 0; nt < 8; nt++) {
                const int col = col0 + wn * 64 + nt * 8 + ocol2;
                float2 v;
                if (MODE == 3) {
                    v.x = ik * acc[mt][nt][half * 2 + 0] + bias[col];
                    v.y = ik * acc[mt][nt][half * 2 + 1] + bias[col + 1];
                    if (live) {
                        const float2 q2 = *reinterpret_cast<const float2*>(
                            A2 + tok * DM + col);
                        v.x += iq * q2.x; v.y += iq * q2.y;
                    }
                } else {
                    v.x = acc[mt][nt][half * 2 + 0] + bias[col];
                    v.y = acc[mt][nt][half * 2 + 1] + bias[col + 1];
                    if (MODE == 4) {
                        const float2 r2 = *reinterpret_cast<const float2*>(
                            E0 + (size_t)m * DM + col);
                        v.x += r2.x; v.y += r2.y;
                    }
                }
                if (MODE == 1 || MODE == 2) {
                    pss[mt][half] += v.x * v.x + v.y * v.y;
                    if (MODE == 1) {
                        pdot[mt][half] += v.x * __ldg(E0 + col)
                                        + v.y * __ldg(E0 + col + 1);
                    }
                }
                if (live)
                    *reinterpret_cast<float2*>(C + crow * DM + col) = v;
            }
        }
    }

    // ---- per-row partial reduction (MODE 1/2) ----
    if (MODE == 1 || MODE == 2) {
#pragma unroll
        for (int off = 1; off <= 2; off <<= 1) {
#pragma unroll
            for (int a = 0; a < 2; a++)
#pragma unroll
                for (int h = 0; h < 2; h++) {
                    pss[a][h]  += __shfl_xor_sync(0xffffffffu, pss[a][h],  off);
                    pdot[a][h] += __shfl_xor_sync(0xffffffffu, pdot[a][h], off);
                }
        }
        if ((lane & 3) == 0) {
#pragma unroll
            for (int a = 0; a < 2; a++)
#pragma unroll
                for (int h = 0; h < 2; h++) {
                    const int rib = wm * 32 + a * 16 + orow + h * 8;
                    sred[rib][wn] = make_float2(pss[a][h], pdot[a][h]);
                }
        }
        __syncthreads();
        if (tid < 128) {
            const float2 u0 = sred[tid][0];
            const float2 u1 = sred[tid][1];
            PP[(size_t)(row0 + tid) * 4 + blockIdx.x] =
                make_float2(u0.x + u1.x, u0.y + u1.y);
        }
    }
}

// ---------------------------------------------------------------------------
// Reduce per-colblock partials -> inv_q, inv_k, logits.
// ---------------------------------------------------------------------------
__global__ void __launch_bounds__(256) invlog_k() {
    const int t = blockIdx.x * 256 + threadIdx.x;
    if (t >= BATCH * NTOK) return;
    float ssq = 0.f, dot = 0.f, ssk = 0.f;
#pragma unroll
    for (int i = 0; i < 4; i++) {
        const float2 pq = g_PQ[(size_t)t * 4 + i];
        ssq += pq.x; dot += pq.y;
        ssk += g_PK[(size_t)t * 4 + i].x;
    }
    const float iq = 1.f / fmaxf(sqrtf(ssq), 1e-12f);
    g_IQ[t] = iq;
    g_IK[t] = 1.f / fmaxf(sqrtf(ssk), 1e-12f);
    g_L[t]  = dot * iq * SOFTMAX_SCALE;
}

// ---------------------------------------------------------------------------
// Per-batch softmax over logits; output a'[n] = softmax[n] * inv_q[n].
// ---------------------------------------------------------------------------
__global__ void __launch_bounds__(512) softmax_k() {
    __shared__ float sd[NTOK];
    __shared__ float red[32];
    const int b    = blockIdx.x;
    const int tid  = threadIdx.x;
    const int warp = tid >> 5;
    const int lane = tid & 31;
    float* Lb = g_L + (size_t)b * NTOK;

    for (int n = tid; n < NTOK; n += 512) sd[n] = Lb[n];
    __syncthreads();

    float m = -1e30f;
    for (int n = tid; n < NTOK; n += 512) m = fmaxf(m, sd[n]);
#pragma unroll
    for (int o = 16; o; o >>= 1) m = fmaxf(m, __shfl_xor_sync(0xffffffffu, m, o));
    if (lane == 0) red[warp] = m;
    __syncthreads();
    if (tid < 32) {
        float t = (tid < 16) ? red[tid] : -1e30f;
#pragma unroll
        for (int o = 8; o; o >>= 1) t = fmaxf(t, __shfl_xor_sync(0xffffffffu, t, o));
        if (tid == 0) red[16] = t;
    }
    __syncthreads();
    m = red[16];

    float s = 0.f;
    for (int n = tid; n < NTOK; n += 512) {
        float e = expf(sd[n] - m);
        sd[n] = e;
        s += e;
    }
#pragma unroll
    for (int o = 16; o; o >>= 1) s += __shfl_xor_sync(0xffffffffu, s, o);
    if (lane == 0) red[warp] = s;
    __syncthreads();
    if (tid < 32) {
        float t = (tid < 16) ? red[tid] : 0.f;
#pragma unroll
        for (int o = 8; o; o >>= 1) t += __shfl_xor_sync(0xffffffffu, t, o);
        if (tid == 0) red[17] = t;
    }
    __syncthreads();
    const float inv = 1.f / red[17];
    for (int n = tid; n < NTOK; n += 512)
        Lb[n] = sd[n] * inv * g_IQ[(size_t)b * NTOK + n];
}

// ---------------------------------------------------------------------------
// g = sum_n a'[n] * Q_raw[n,:]  (deterministic two-stage reduce)
// ---------------------------------------------------------------------------
__global__ void __launch_bounds__(512) greduce_k() {
    const int b = blockIdx.x;
    const int s = blockIdx.y;
    const int d = threadIdx.x;
    const int n0 = s * SLROWS;
    const int n1 = (n0 + SLROWS < NTOK) ? n0 + SLROWS : NTOK;
    const float* Qb = g_Q + (size_t)b * NTOK * DM;
    const float* Lb = g_L + (size_t)b * NTOK;
    float a = 0.f;
    for (int n = n0; n < n1; n++)
        a += Lb[n] * Qb[(size_t)n * DM + d];
    g_Gp[((size_t)s * BATCH + b) * DM + d] = a;
}

__global__ void __launch_bounds__(512) combine_k() {
    const int b = blockIdx.x;
    const int d = threadIdx.x;
    float a = 0.f;
#pragma unroll
    for (int s = 0; s < NSLICE; s++)
        a += g_Gp[((size_t)s * BATCH + b) * DM + d];
    g_G[(size_t)b * DM + d] = a;
}

// ---------------------------------------------------------------------------
// Wg[b] = g_b (.) proj_w   (float4 elementwise)
// ---------------------------------------------------------------------------
__global__ void __launch_bounds__(256) wgscale_k(const float* __restrict__ PW) {
    const size_t i = (size_t)blockIdx.x * 256 + threadIdx.x;   // float4 idx
    const size_t per_b = (size_t)DM * DM / 4;                  // 65536
    if (i >= (size_t)BATCH * per_b) return;
    const size_t b = i / per_b;
    const size_t r = i - b * per_b;
    float4 w = reinterpret_cast<const float4*>(PW)[r];
    const float4 gg = reinterpret_cast<const float4*>(g_G)[b * (DM / 4) + (r & (DM / 4 - 1))];
    w.x *= gg.x; w.y *= gg.y; w.z *= gg.z; w.w *= gg.w;
    reinterpret_cast<float4*>(g_W)[i] = w;
}

// ---------------------------------------------------------------------------
// Launch pipeline (graph-capturable: kernels only).
// ---------------------------------------------------------------------------
extern "C" void kernel_launch(void* const* d_in, const int* in_sizes, int n_in,
                              void* d_out, int out_size) {
    const float* verts   = (const float*)d_in[0];
    const float* imgf    = (const float*)d_in[1];
    const float* fc_w    = (const float*)d_in[2];
    const float* fc_b    = (const float*)d_in[3];
    const float* q_w     = (const float*)d_in[4];
    const float* q_b     = (const float*)d_in[5];
    const float* k_w     = (const float*)d_in[6];
    const float* k_b     = (const float*)d_in[7];
    const float* w_g     = (const float*)d_in[8];
    const float* proj_w  = (const float*)d_in[9];
    const float* proj_b  = (const float*)d_in[10];
    const float* final_w = (const float*)d_in[11];
    const float* final_b = (const float*)d_in[12];
    float* out = (float*)d_out;

    float *Q, *K, *Cimg, *P, *Wg, *IK, *IQ;
    float2 *PQ, *PK;
    cudaGetSymbolAddress((void**)&Q,    g_Q);
    cudaGetSymbolAddress((void**)&K,    g_K);
    cudaGetSymbolAddress((void**)&Cimg, g_C);
    cudaGetSymbolAddress((void**)&P,    g_P);
    cudaGetSymbolAddress((void**)&Wg,   g_W);
    cudaGetSymbolAddress((void**)&IK,   g_IK);
    cudaGetSymbolAddress((void**)&IQ,   g_IQ);
    cudaGetSymbolAddress((void**)&PQ,   g_PQ);
    cudaGetSymbolAddress((void**)&PK,   g_PK);

    cudaFuncSetAttribute(ca_gemm_k<0>, cudaFuncAttributeMaxDynamicSharedMemorySize, SMEM_CA);
    cudaFuncSetAttribute(ca_gemm_k<1>, cudaFuncAttributeMaxDynamicSharedMemorySize, SMEM_CA);
    cudaFuncSetAttribute(ca_gemm_k<2>, cudaFuncAttributeMaxDynamicSharedMemorySize, SMEM_CA);
    cudaFuncSetAttribute(ca_gemm_k<3>, cudaFuncAttributeMaxDynamicSharedMemorySize, SMEM_CA);
    cudaFuncSetAttribute(ca_gemm_k<4>, cudaFuncAttributeMaxDynamicSharedMemorySize, SMEM_CA);

    // imgC = img_f @ fc_w^T + fc_b   (compact [B*NI, DM])
    ca_gemm_k<0><<<dim3(4, (BATCH * NI) / 128), 256, SMEM_CA>>>(
        imgf, nullptr, fc_w, fc_b, Cimg, IMGD, nullptr, nullptr, nullptr);

    // raw q/k over all tokens (A rows remapped from verts/imgC);
    // epilogues write per-colblock (sumsq, dot) partials
    ca_gemm_k<1><<<dim3(4, (BATCH * NTOK) / 128), 256, SMEM_CA>>>(
        verts, Cimg, q_w, q_b, Q, DM, w_g, nullptr, PQ);
    ca_gemm_k<2><<<dim3(4, (BATCH * NTOK) / 128), 256, SMEM_CA>>>(
        verts, Cimg, k_w, k_b, K, DM, nullptr, nullptr, PK);

    // inv norms + logits; softmax -> a' (weights * inv_q); g reduce
    invlog_k<<<(BATCH * NTOK + 255) / 256, 256>>>();
    softmax_k<<<BATCH, 512>>>();
    greduce_k<<<dim3(BATCH, NSLICE), 512>>>();
    combine_k<<<BATCH, 512>>>();

    // per-batch scaled weights Wg[b] = g_b (.) proj_w
    wgscale_k<<<(BATCH * DM * DM / 4 + 255) / 256, 256>>>(proj_w);

    // out = norm(k) @ Wg[b]^T + proj_b + norm(q)   (per-batch tiles, compact P)
    ca_gemm_k<3><<<dim3(4, MB_PROJ, BATCH), 256, SMEM_CA>>>(
        K, Q, Wg, proj_b, P, DM, IK, IQ, nullptr);

    // final = P @ final_w^T + final_b + verts  -> d_out
    ca_gemm_k<4><<<dim3(4, (BATCH * NV) / 128), 256, SMEM_CA>>>(
        P, nullptr, final_w, final_b, out, DM, verts, nullptr, nullptr);
}